// round 12
// baseline (speedup 1.0000x reference)
#include <cuda_runtime.h>
#include <cuda_bf16.h>
#include <mma.h>
#include <math.h>
#include <stdint.h>

using namespace nvcuda;

#define B 64
#define T 512
#define D 1024
#define RBLK 128          // recurrence grid: 32 n-splits x 4 b-splits

// ---------------- wx GEMM config (K-concat hi/lo trick, K'=3072) ----------------
#define KK 3072
#define BM 128
#define BN 128
#define BK 32
#define NK (KK / BK)
#define LDT 40
#define STAGE_A (BM * LDT * 2)
#define AB_STAGES 3
#define SMEM_B_OFF (AB_STAGES * STAGE_A)
#define SMEM_BIAS_OFF (2 * AB_STAGES * STAGE_A)
#define GEMM_SMEM (SMEM_BIAS_OFF + 16 * BN * 4)

// ---------------- recurrence smem config ----------------
#define ULD 1032                               // padded k-stride (bf16 elems)
#define U_ELEMS (32 * ULD)                     // 32 n-rows x 1032
#define H_ELEMS (16 * ULD)                     // 16 b-rows x 1032
#define U_REGION (2 * U_ELEMS * 2)             // 132096 B; dead after frag pinning
// layout: [U region (aliased: s_red[2][8][512] | s_wx[3][512])] | s_hhi | s_hlo
#define RNN_SMEM (U_REGION + 2 * H_ELEMS * 2)  // 198144 B

// ---------------- scratch ----------------
__device__ unsigned g_flags[4][32][8][8];              // per-(bi,ni,warp) step flags, 32B padded
__device__ __nv_bfloat16 g_xs[(size_t)B * T * KK];     // x split K-concat [hi|lo|hi]
__device__ __nv_bfloat16 g_ws[(size_t)D * KK];         // W split K-concat [hi|hi|lo]
__device__ __nv_bfloat16 g_hhi[2][B * D];              // h hi, double buffered
__device__ __nv_bfloat16 g_hlo[2][B * D];              // h lo
__device__ __nv_bfloat16 g_uhi[D * D];                 // U hi, row-major [n][k]
__device__ __nv_bfloat16 g_ulo[D * D];                 // U lo

// ---------------- helpers ----------------
__device__ __forceinline__ uint32_t smem_u32(const void* p) {
    uint32_t a;
    asm("{ .reg .u64 t; cvta.to.shared.u64 t, %1; cvt.u32.u64 %0, t; }" : "=r"(a) : "l"(p));
    return a;
}
__device__ __forceinline__ void cp_async16(uint32_t dst, const void* src) {
    asm volatile("cp.async.cg.shared.global [%0], [%1], 16;" :: "r"(dst), "l"(src) : "memory");
}
#define CP_COMMIT() asm volatile("cp.async.commit_group;" ::: "memory")

// ---------------- init: zero h0 and the exchange flags ----------------
__global__ void zero_h0() {
    int i = blockIdx.x * blockDim.x + threadIdx.x;
    if (i < B * D) {
        g_hhi[0][i] = __nv_bfloat16(0.f);
        g_hlo[0][i] = __nv_bfloat16(0.f);
    }
    if (i < 4 * 32 * 8) g_flags[i >> 8][(i >> 3) & 31][i & 7][0] = 0;
}

// ---------------- fp32 -> bf16 splits ----------------
__global__ void split_x(const float* __restrict__ s) {
    size_t i = (size_t)blockIdx.x * blockDim.x + threadIdx.x;
    float4 v = ((const float4*)s)[i];
    size_t e = i * 4;
    size_t m = e >> 10;
    int    k = (int)(e & 1023);
    __nv_bfloat16 hx = __float2bfloat16(v.x), hy = __float2bfloat16(v.y);
    __nv_bfloat16 hz = __float2bfloat16(v.z), hw = __float2bfloat16(v.w);
    __nv_bfloat162 h01(hx, hy), h23(hz, hw);
    __nv_bfloat162 l01(__float2bfloat16(v.x - __bfloat162float(hx)),
                       __float2bfloat16(v.y - __bfloat162float(hy)));
    __nv_bfloat162 l23(__float2bfloat16(v.z - __bfloat162float(hz)),
                       __float2bfloat16(v.w - __bfloat162float(hw)));
    __nv_bfloat16* row = g_xs + m * KK;
    *(__nv_bfloat162*)(row + k)       = h01;  *(__nv_bfloat162*)(row + k + 2)       = h23;
    *(__nv_bfloat162*)(row + D + k)   = l01;  *(__nv_bfloat162*)(row + D + k + 2)   = l23;
    *(__nv_bfloat162*)(row + 2*D + k) = h01;  *(__nv_bfloat162*)(row + 2*D + k + 2) = h23;
}
__global__ void split_w(const float* __restrict__ s) {
    size_t i = (size_t)blockIdx.x * blockDim.x + threadIdx.x;
    float4 v = ((const float4*)s)[i];
    size_t e = i * 4;
    size_t n = e >> 10;
    int    k = (int)(e & 1023);
    __nv_bfloat16 hx = __float2bfloat16(v.x), hy = __float2bfloat16(v.y);
    __nv_bfloat16 hz = __float2bfloat16(v.z), hw = __float2bfloat16(v.w);
    __nv_bfloat162 h01(hx, hy), h23(hz, hw);
    __nv_bfloat162 l01(__float2bfloat16(v.x - __bfloat162float(hx)),
                       __float2bfloat16(v.y - __bfloat162float(hy)));
    __nv_bfloat162 l23(__float2bfloat16(v.z - __bfloat162float(hz)),
                       __float2bfloat16(v.w - __bfloat162float(hw)));
    __nv_bfloat16* row = g_ws + n * KK;
    *(__nv_bfloat162*)(row + k)       = h01;  *(__nv_bfloat162*)(row + k + 2)       = h23;
    *(__nv_bfloat162*)(row + D + k)   = h01;  *(__nv_bfloat162*)(row + D + k + 2)   = h23;
    *(__nv_bfloat162*)(row + 2*D + k) = l01;  *(__nv_bfloat162*)(row + 2*D + k + 2) = l23;
}
__global__ void split_U(const float* __restrict__ s) {
    size_t i = (size_t)blockIdx.x * blockDim.x + threadIdx.x;
    float4 v = ((const float4*)s)[i];
    __nv_bfloat16 hx = __float2bfloat16(v.x), hy = __float2bfloat16(v.y);
    __nv_bfloat16 hz = __float2bfloat16(v.z), hw = __float2bfloat16(v.w);
    ((__nv_bfloat162*)g_uhi)[2*i]   = __nv_bfloat162(hx, hy);
    ((__nv_bfloat162*)g_uhi)[2*i+1] = __nv_bfloat162(hz, hw);
    ((__nv_bfloat162*)g_ulo)[2*i]   = __nv_bfloat162(__float2bfloat16(v.x - __bfloat162float(hx)),
                                                     __float2bfloat16(v.y - __bfloat162float(hy)));
    ((__nv_bfloat162*)g_ulo)[2*i+1] = __nv_bfloat162(__float2bfloat16(v.z - __bfloat162float(hz)),
                                                     __float2bfloat16(v.w - __bfloat162float(hw)));
}

// ================= wx = x @ W^T + Wb via wmma (now 2 CTAs/SM) =================
__device__ __forceinline__ void fill_stage(uint32_t sb, int s, int m0, int n0, int k0, int tid) {
    uint32_t sa = sb + s * STAGE_A;
    uint32_t sbb = sb + SMEM_B_OFF + s * STAGE_A;
    #pragma unroll
    for (int j = 0; j < 2; ++j) {
        int idx = tid + j * 256;
        int r = idx >> 2, c = idx & 3;
        cp_async16(sa + r * (LDT * 2) + c * 16, g_xs + (size_t)(m0 + r) * KK + k0 + c * 8);
    }
    #pragma unroll
    for (int j = 0; j < 2; ++j) {
        int idx = tid + j * 256;
        int r = idx >> 2, c = idx & 3;
        cp_async16(sbb + r * (LDT * 2) + c * 16, g_ws + (size_t)(n0 + r) * KK + k0 + c * 8);
    }
    CP_COMMIT();
}

__global__ void __launch_bounds__(256, 2) gemm_wx_mma(float* __restrict__ out,
                                                      const float* __restrict__ Wb) {
    extern __shared__ char smem[];
    uint32_t sb = smem_u32(smem);
    float* biasT = (float*)(smem + SMEM_BIAS_OFF);
    const int tid = threadIdx.x, warp = tid >> 5;
    const int wm = warp & 3, wn = warp >> 2;
    const int n0 = blockIdx.x * BN, m0 = blockIdx.y * BM;

    for (int i = tid; i < 16 * BN; i += 256) biasT[i] = Wb[n0 + (i & (BN - 1))];
    __syncthreads();

    wmma::fragment<wmma::accumulator, 16, 16, 16, float> c[2][4];
    #pragma unroll
    for (int i = 0; i < 2; ++i)
        #pragma unroll
        for (int j = 0; j < 4; ++j)
            wmma::load_matrix_sync(c[i][j], biasT + wn * 64 + j * 16, BN, wmma::mem_row_major);

    fill_stage(sb, 0, m0, n0, 0, tid);
    fill_stage(sb, 1, m0, n0, BK, tid);

    int rs = 0, ws = 2;
    for (int ks = 0; ks < NK; ++ks) {
        asm volatile("cp.async.wait_group 1;" ::: "memory");
        __syncthreads();

        const __nv_bfloat16* As = (const __nv_bfloat16*)(smem + rs * STAGE_A);
        const __nv_bfloat16* Bs = (const __nv_bfloat16*)(smem + SMEM_B_OFF + rs * STAGE_A);
        #pragma unroll
        for (int kk = 0; kk < 2; ++kk) {
            wmma::fragment<wmma::matrix_a, 16, 16, 16, __nv_bfloat16, wmma::row_major> a[2];
            wmma::fragment<wmma::matrix_b, 16, 16, 16, __nv_bfloat16, wmma::col_major> b[4];
            #pragma unroll
            for (int i = 0; i < 2; ++i)
                wmma::load_matrix_sync(a[i], As + (wm * 32 + i * 16) * LDT + kk * 16, LDT);
            #pragma unroll
            for (int j = 0; j < 4; ++j)
                wmma::load_matrix_sync(b[j], Bs + (wn * 64 + j * 16) * LDT + kk * 16, LDT);
            #pragma unroll
            for (int i = 0; i < 2; ++i)
                #pragma unroll
                for (int j = 0; j < 4; ++j)
                    wmma::mma_sync(c[i][j], a[i], b[j], c[i][j]);
        }

        if (ks + 2 < NK) fill_stage(sb, ws, m0, n0, (ks + 2) * BK, tid);
        else CP_COMMIT();
        rs = (rs == 2) ? 0 : rs + 1;
        ws = (ws == 2) ? 0 : ws + 1;
    }

    #pragma unroll
    for (int i = 0; i < 2; ++i)
        #pragma unroll
        for (int j = 0; j < 4; ++j)
            wmma::store_matrix_sync(out + (size_t)(m0 + wm * 32 + i * 16) * D + n0 + wn * 64 + j * 16,
                                    c[i][j], D, wmma::mem_row_major);
}

// ================= persistent HMMA recurrence: slab-pipelined exchange =================
// 128 blocks x 256 threads. Block (ni, bi): n-cols [ni*32,+32), batches [bi*16,+16).
// U pinned in registers. Per step each warp handles its 128-k range as FOUR 32-k
// slabs (one per producer block): poll that block's 8 warp flags, cp.async the
// slab, commit; then drain with wait_group 4->3->2->1, overlapping slab r's MMA
// with slabs r+1.. in flight. wx[t] completes at the first wait (in-order groups).
__global__ void __launch_bounds__(256, 1) rnn_mma(float* __restrict__ out,
                                                  const float* __restrict__ Ub,
                                                  const float* __restrict__ bias) {
    extern __shared__ char sm[];
    __nv_bfloat16* s_uhi = (__nv_bfloat16*)sm;             // [32][ULD] (init only)
    __nv_bfloat16* s_ulo = s_uhi + U_ELEMS;
    __nv_bfloat16* s_hhi = (__nv_bfloat16*)(sm + U_REGION); // [16][ULD], warp-private slabs
    __nv_bfloat16* s_hlo = s_hhi + H_ELEMS;
    float* s_red = (float*)sm;                             // ALIAS of U region: [2][8][512]
    float* s_wx  = s_red + 2 * 8 * 512;                    // [3][512]

    const int tid = threadIdx.x, warp = tid >> 5, lane = tid & 31;
    const int ni = blockIdx.x >> 2, bi = blockIdx.x & 3;
    const int n0 = ni * 32, b0 = bi * 16;

    // ---- stage U slice once ----
    {
        uint32_t duh = smem_u32(s_uhi), dul = smem_u32(s_ulo);
        for (int i = tid; i < 32 * 128; i += 256) {
            int r = i >> 7, c = i & 127;
            cp_async16(duh + (r * ULD + c * 8) * 2, g_uhi + (size_t)(n0 + r) * D + c * 8);
            cp_async16(dul + (r * ULD + c * 8) * 2, g_ulo + (size_t)(n0 + r) * D + c * 8);
        }
        CP_COMMIT();
        asm volatile("cp.async.wait_group 0;" ::: "memory");
        __syncthreads();
    }

    const int kc0 = warp * 128;

    // register-pinned U fragments (loaded before the alias region is written)
    wmma::fragment<wmma::matrix_b, 16, 16, 16, __nv_bfloat16, wmma::col_major> pbh[8][2], pbl[8][2];
    #pragma unroll
    for (int ks = 0; ks < 8; ++ks) {
        const int kg = kc0 + ks * 16;
        #pragma unroll
        for (int j = 0; j < 2; ++j) {
            wmma::load_matrix_sync(pbh[ks][j], s_uhi + (size_t)(j * 16) * ULD + kg, ULD);
            wmma::load_matrix_sync(pbl[ks][j], s_ulo + (size_t)(j * 16) * ULD + kg, ULD);
        }
    }
    __syncthreads();   // U smem region may now be reused (s_red/s_wx alias)

    const uint32_t shh = smem_u32(s_hhi), shl = smem_u32(s_hlo);
    const uint32_t swx = smem_u32(s_wx);

    unsigned* pubflag = &g_flags[bi][ni][warp][0];

    // ---- wx prefetch geometry ----
    const int pr = tid >> 3, pc = tid & 7;
    const float* wx_src0 = out + (size_t)(b0 + pr) * (T * D) + n0 + pc * 4;
    const uint32_t wx_doff = (pr * 32 + pc * 4) * 4;

    // ---- epilogue constants ----
    const int eb  = tid >> 4;
    const int enl = (tid & 15) * 2;
    float2 cconst;
    cconst.x = Ub[n0 + enl]     + bias[n0 + enl];
    cconst.y = Ub[n0 + enl + 1] + bias[n0 + enl + 1];
    const size_t obase = (size_t)(b0 + eb) * (T * D) + n0 + enl;
    const int    hbase = (b0 + eb) * D + n0 + enl;
    const int    efr   = enl >> 4;
    const int    ec    = enl & 15;

    // slab staging geometry: lanes move 2 x 16B chunks per matrix per slab
    // slab = 16 rows x 32 k hi+lo = 64 chunks per matrix
    // i = lane + j*32 (j=0,1): row = i>>2, chunk = i&3

    // ---- prologue: prefetch wx[0] (group stays pending into t=0) ----
    if (tid < 128) cp_async16(swx + wx_doff, wx_src0);
    CP_COMMIT();

    int wb = 0;                                   // t % 3
    for (int t = 0; t < T; ++t) {
        const __nv_bfloat16* Hhi = g_hhi[t & 1];
        const __nv_bfloat16* Hlo = g_hlo[t & 1];
        const int nwb = (wb == 2) ? 0 : wb + 1;   // (t+1) % 3

        // ---- 4 rounds: poll producer block r, stage its 32-k slab, commit ----
        #pragma unroll
        for (int r = 0; r < 4; ++r) {
            if (lane < 8) {
                unsigned* f = &g_flags[bi][(warp << 2) + r][lane][0];
                unsigned v;
                do {
                    asm volatile("ld.acquire.gpu.global.u32 %0, [%1];" : "=r"(v) : "l"(f) : "memory");
                } while (v < (unsigned)t);
            }
            __syncwarp();
            const int k0 = kc0 + r * 32;
            #pragma unroll
            for (int j = 0; j < 2; ++j) {
                int i = lane + j * 32;          // 0..63
                int rr = i >> 2, cc = i & 3;    // row 0..15, chunk 0..3
                uint32_t off = (rr * ULD + k0 + cc * 8) * 2;
                const size_t goff = (size_t)(b0 + rr) * D + k0 + cc * 8;
                cp_async16(shh + off, Hhi + goff);
                cp_async16(shl + off, Hlo + goff);
            }
            CP_COMMIT();
        }

        // ---- prefetch wx[t+1] (own group; stays pending into t+1) ----
        if (t + 1 < T && tid < 128)
            cp_async16(swx + nwb * 2048 + wx_doff, wx_src0 + (size_t)(t + 1) * D);
        CP_COMMIT();

        // ---- drain pipeline: mma slab r while slabs r+1.. fly ----
        wmma::fragment<wmma::accumulator, 16, 16, 16, float> acc[2];
        wmma::fill_fragment(acc[0], 0.f);
        wmma::fill_fragment(acc[1], 0.f);

        #define MMA_SLAB(r, wg)                                                       \
        do {                                                                          \
            asm volatile("cp.async.wait_group " #wg ";" ::: "memory");                \
            __syncwarp();                                                             \
            _Pragma("unroll")                                                         \
            for (int ks = 2 * (r); ks < 2 * (r) + 2; ++ks) {                          \
                const int kg = kc0 + ks * 16;                                         \
                wmma::fragment<wmma::matrix_a, 16, 16, 16, __nv_bfloat16,             \
                               wmma::row_major> ah, al;                               \
                wmma::load_matrix_sync(ah, s_hhi + kg, ULD);                          \
                wmma::load_matrix_sync(al, s_hlo + kg, ULD);                          \
                _Pragma("unroll")                                                     \
                for (int j = 0; j < 2; ++j) {                                         \
                    wmma::mma_sync(acc[j], ah, pbh[ks][j], acc[j]);                   \
                    wmma::mma_sync(acc[j], al, pbh[ks][j], acc[j]);                   \
                    wmma::mma_sync(acc[j], ah, pbl[ks][j], acc[j]);                   \
                }                                                                     \
            }                                                                         \
        } while (0)

        MMA_SLAB(0, 4);   // also completes wx[t] (in-order)
        MMA_SLAB(1, 3);
        MMA_SLAB(2, 2);
        MMA_SLAB(3, 1);   // wx[t+1] remains pending
        #undef MMA_SLAB

        float* red = s_red + (t & 1) * 4096;
        wmma::store_matrix_sync(red + warp * 512,       acc[0], 16, wmma::mem_row_major);
        wmma::store_matrix_sync(red + warp * 512 + 256, acc[1], 16, wmma::mem_row_major);
        __syncthreads();   // the ONE block sync per step

        // ---- 8-way K reduction + epilogue: h stores -> flag -> out store ----
        {
            const float* p = red + efr * 256 + eb * 16 + ec;
            float s0 = 0.f, s1 = 0.f;
            #pragma unroll
            for (int w = 0; w < 8; ++w) { s0 += p[w * 512]; s1 += p[w * 512 + 1]; }
            const float* wxp = s_wx + wb * 512 + eb * 32 + enl;
            float zx = tanhf(wxp[0] + s0 + cconst.x);
            float zy = tanhf(wxp[1] + s1 + cconst.y);

            // h stores FIRST (these are what consumers need)
            __nv_bfloat16 hx = __float2bfloat16(zx), hy = __float2bfloat16(zy);
            *(__nv_bfloat162*)(g_hhi[(t + 1) & 1] + hbase) = __nv_bfloat162(hx, hy);
            *(__nv_bfloat162*)(g_hlo[(t + 1) & 1] + hbase) =
                __nv_bfloat162(__float2bfloat16(zx - __bfloat162float(hx)),
                               __float2bfloat16(zy - __bfloat162float(hy)));
            __syncwarp();
            if (lane == 0)
                asm volatile("st.release.gpu.global.u32 [%0], %1;"
                             :: "l"(pubflag), "r"((unsigned)(t + 1)) : "memory");

            // out store off the critical path
            *(float2*)(out + obase + (size_t)t * D) = make_float2(zx, zy);
            if (t == T - 1)   // fused copy_hx
                *(float2*)(out + (size_t)B * T * D + hbase) = make_float2(zx, zy);
        }
        wb = nwb;
    }
}

extern "C" void kernel_launch(void* const* d_in, const int* in_sizes, int n_in,
                              void* d_out, int out_size) {
    const float* x    = (const float*)d_in[0];
    const float* Ww   = (const float*)d_in[1];
    const float* Wb   = (const float*)d_in[2];
    const float* Uw   = (const float*)d_in[3];
    const float* Ub   = (const float*)d_in[4];
    const float* bias = (const float*)d_in[5];
    float* out = (float*)d_out;

    cudaFuncSetAttribute(gemm_wx_mma, cudaFuncAttributeMaxDynamicSharedMemorySize, GEMM_SMEM);
    cudaFuncSetAttribute(rnn_mma,     cudaFuncAttributeMaxDynamicSharedMemorySize, RNN_SMEM);

    zero_h0<<<(B * D + 255) / 256, 256>>>();
    split_x<<<((size_t)B * T * D / 4) / 256, 256>>>(x);
    split_w<<<(D * D / 4) / 256, 256>>>(Ww);
    split_U<<<(D * D / 4) / 256, 256>>>(Uw);
    gemm_wx_mma<<<dim3(D / BN, (B * T) / BM), 256, GEMM_SMEM>>>(out, Wb);
    rnn_mma<<<RBLK, 256, RNN_SMEM>>>(out, Ub, bias);
}

// round 13
// speedup vs baseline: 1.3101x; 1.3101x over previous
#include <cuda_runtime.h>
#include <cuda_bf16.h>
#include <mma.h>
#include <math.h>
#include <stdint.h>

using namespace nvcuda;

#define B 64
#define T 512
#define D 1024
#define RBLK 128          // recurrence grid: 32 n-splits x 4 b-splits

// ---------------- wx GEMM config (K-concat hi/lo trick, K'=3072) ----------------
#define KK 3072
#define BM 128
#define BN 128
#define BK 32
#define NK (KK / BK)
#define LDT 40
#define STAGE_A (BM * LDT * 2)
#define AB_STAGES 3
#define SMEM_B_OFF (AB_STAGES * STAGE_A)
#define SMEM_BIAS_OFF (2 * AB_STAGES * STAGE_A)
#define GEMM_SMEM (SMEM_BIAS_OFF + 16 * BN * 4)

// ---------------- recurrence smem config ----------------
#define ULD 1032                               // padded k-stride (bf16 elems)
#define U_ELEMS (32 * ULD)                     // 32 n-rows x 1032
#define H_ELEMS (16 * ULD)                     // 16 b-rows x 1032
#define U_REGION (2 * U_ELEMS * 2)             // 132096 B; dead after frag pinning
// layout: [U region (aliased: s_red[2][8][512] | s_wx[3][512])] | s_hhi | s_hlo
#define RNN_SMEM (U_REGION + 2 * H_ELEMS * 2)  // 198144 B

// ---------------- scratch ----------------
__device__ unsigned g_flags[4][32][8][8];              // per-(bi,ni,warp) step flags, 32B padded
__device__ __nv_bfloat16 g_xs[(size_t)B * T * KK];     // x split K-concat [hi|lo|hi]
__device__ __nv_bfloat16 g_ws[(size_t)D * KK];         // W split K-concat [hi|hi|lo]
__device__ __nv_bfloat16 g_hhi[2][B * D];              // h hi, double buffered
__device__ __nv_bfloat16 g_hlo[2][B * D];              // h lo
__device__ __nv_bfloat16 g_uhi[D * D];                 // U hi, row-major [n][k]
__device__ __nv_bfloat16 g_ulo[D * D];                 // U lo

// ---------------- helpers ----------------
__device__ __forceinline__ uint32_t smem_u32(const void* p) {
    uint32_t a;
    asm("{ .reg .u64 t; cvta.to.shared.u64 t, %1; cvt.u32.u64 %0, t; }" : "=r"(a) : "l"(p));
    return a;
}
__device__ __forceinline__ void cp_async16(uint32_t dst, const void* src) {
    asm volatile("cp.async.cg.shared.global [%0], [%1], 16;" :: "r"(dst), "l"(src) : "memory");
}
#define CP_COMMIT() asm volatile("cp.async.commit_group;" ::: "memory")

// ---------------- init: zero h0 and the exchange flags ----------------
__global__ void zero_h0() {
    int i = blockIdx.x * blockDim.x + threadIdx.x;
    if (i < B * D) {
        g_hhi[0][i] = __nv_bfloat16(0.f);
        g_hlo[0][i] = __nv_bfloat16(0.f);
    }
    if (i < 4 * 32 * 8) g_flags[i >> 8][(i >> 3) & 31][i & 7][0] = 0;
}

// ---------------- fp32 -> bf16 splits ----------------
__global__ void split_x(const float* __restrict__ s) {
    size_t i = (size_t)blockIdx.x * blockDim.x + threadIdx.x;
    float4 v = ((const float4*)s)[i];
    size_t e = i * 4;
    size_t m = e >> 10;
    int    k = (int)(e & 1023);
    __nv_bfloat16 hx = __float2bfloat16(v.x), hy = __float2bfloat16(v.y);
    __nv_bfloat16 hz = __float2bfloat16(v.z), hw = __float2bfloat16(v.w);
    __nv_bfloat162 h01(hx, hy), h23(hz, hw);
    __nv_bfloat162 l01(__float2bfloat16(v.x - __bfloat162float(hx)),
                       __float2bfloat16(v.y - __bfloat162float(hy)));
    __nv_bfloat162 l23(__float2bfloat16(v.z - __bfloat162float(hz)),
                       __float2bfloat16(v.w - __bfloat162float(hw)));
    __nv_bfloat16* row = g_xs + m * KK;
    *(__nv_bfloat162*)(row + k)       = h01;  *(__nv_bfloat162*)(row + k + 2)       = h23;
    *(__nv_bfloat162*)(row + D + k)   = l01;  *(__nv_bfloat162*)(row + D + k + 2)   = l23;
    *(__nv_bfloat162*)(row + 2*D + k) = h01;  *(__nv_bfloat162*)(row + 2*D + k + 2) = h23;
}
__global__ void split_w(const float* __restrict__ s) {
    size_t i = (size_t)blockIdx.x * blockDim.x + threadIdx.x;
    float4 v = ((const float4*)s)[i];
    size_t e = i * 4;
    size_t n = e >> 10;
    int    k = (int)(e & 1023);
    __nv_bfloat16 hx = __float2bfloat16(v.x), hy = __float2bfloat16(v.y);
    __nv_bfloat16 hz = __float2bfloat16(v.z), hw = __float2bfloat16(v.w);
    __nv_bfloat162 h01(hx, hy), h23(hz, hw);
    __nv_bfloat162 l01(__float2bfloat16(v.x - __bfloat162float(hx)),
                       __float2bfloat16(v.y - __bfloat162float(hy)));
    __nv_bfloat162 l23(__float2bfloat16(v.z - __bfloat162float(hz)),
                       __float2bfloat16(v.w - __bfloat162float(hw)));
    __nv_bfloat16* row = g_ws + n * KK;
    *(__nv_bfloat162*)(row + k)       = h01;  *(__nv_bfloat162*)(row + k + 2)       = h23;
    *(__nv_bfloat162*)(row + D + k)   = h01;  *(__nv_bfloat162*)(row + D + k + 2)   = h23;
    *(__nv_bfloat162*)(row + 2*D + k) = l01;  *(__nv_bfloat162*)(row + 2*D + k + 2) = l23;
}
__global__ void split_U(const float* __restrict__ s) {
    size_t i = (size_t)blockIdx.x * blockDim.x + threadIdx.x;
    float4 v = ((const float4*)s)[i];
    __nv_bfloat16 hx = __float2bfloat16(v.x), hy = __float2bfloat16(v.y);
    __nv_bfloat16 hz = __float2bfloat16(v.z), hw = __float2bfloat16(v.w);
    ((__nv_bfloat162*)g_uhi)[2*i]   = __nv_bfloat162(hx, hy);
    ((__nv_bfloat162*)g_uhi)[2*i+1] = __nv_bfloat162(hz, hw);
    ((__nv_bfloat162*)g_ulo)[2*i]   = __nv_bfloat162(__float2bfloat16(v.x - __bfloat162float(hx)),
                                                     __float2bfloat16(v.y - __bfloat162float(hy)));
    ((__nv_bfloat162*)g_ulo)[2*i+1] = __nv_bfloat162(__float2bfloat16(v.z - __bfloat162float(hz)),
                                                     __float2bfloat16(v.w - __bfloat162float(hw)));
}

// ================= wx = x @ W^T + Wb via wmma — SINGLE CHANGE: 2 CTAs/SM =================
__device__ __forceinline__ void fill_stage(uint32_t sb, int s, int m0, int n0, int k0, int tid) {
    uint32_t sa = sb + s * STAGE_A;
    uint32_t sbb = sb + SMEM_B_OFF + s * STAGE_A;
    #pragma unroll
    for (int j = 0; j < 2; ++j) {
        int idx = tid + j * 256;
        int r = idx >> 2, c = idx & 3;
        cp_async16(sa + r * (LDT * 2) + c * 16, g_xs + (size_t)(m0 + r) * KK + k0 + c * 8);
    }
    #pragma unroll
    for (int j = 0; j < 2; ++j) {
        int idx = tid + j * 256;
        int r = idx >> 2, c = idx & 3;
        cp_async16(sbb + r * (LDT * 2) + c * 16, g_ws + (size_t)(n0 + r) * KK + k0 + c * 8);
    }
    CP_COMMIT();
}

__global__ void __launch_bounds__(256, 2) gemm_wx_mma(float* __restrict__ out,
                                                      const float* __restrict__ Wb) {
    extern __shared__ char smem[];
    uint32_t sb = smem_u32(smem);
    float* biasT = (float*)(smem + SMEM_BIAS_OFF);
    const int tid = threadIdx.x, warp = tid >> 5;
    const int wm = warp & 3, wn = warp >> 2;
    const int n0 = blockIdx.x * BN, m0 = blockIdx.y * BM;

    for (int i = tid; i < 16 * BN; i += 256) biasT[i] = Wb[n0 + (i & (BN - 1))];
    __syncthreads();

    wmma::fragment<wmma::accumulator, 16, 16, 16, float> c[2][4];
    #pragma unroll
    for (int i = 0; i < 2; ++i)
        #pragma unroll
        for (int j = 0; j < 4; ++j)
            wmma::load_matrix_sync(c[i][j], biasT + wn * 64 + j * 16, BN, wmma::mem_row_major);

    fill_stage(sb, 0, m0, n0, 0, tid);
    fill_stage(sb, 1, m0, n0, BK, tid);

    int rs = 0, ws = 2;
    for (int ks = 0; ks < NK; ++ks) {
        asm volatile("cp.async.wait_group 1;" ::: "memory");
        __syncthreads();

        const __nv_bfloat16* As = (const __nv_bfloat16*)(smem + rs * STAGE_A);
        const __nv_bfloat16* Bs = (const __nv_bfloat16*)(smem + SMEM_B_OFF + rs * STAGE_A);
        #pragma unroll
        for (int kk = 0; kk < 2; ++kk) {
            wmma::fragment<wmma::matrix_a, 16, 16, 16, __nv_bfloat16, wmma::row_major> a[2];
            wmma::fragment<wmma::matrix_b, 16, 16, 16, __nv_bfloat16, wmma::col_major> b[4];
            #pragma unroll
            for (int i = 0; i < 2; ++i)
                wmma::load_matrix_sync(a[i], As + (wm * 32 + i * 16) * LDT + kk * 16, LDT);
            #pragma unroll
            for (int j = 0; j < 4; ++j)
                wmma::load_matrix_sync(b[j], Bs + (wn * 64 + j * 16) * LDT + kk * 16, LDT);
            #pragma unroll
            for (int i = 0; i < 2; ++i)
                #pragma unroll
                for (int j = 0; j < 4; ++j)
                    wmma::mma_sync(c[i][j], a[i], b[j], c[i][j]);
        }

        if (ks + 2 < NK) fill_stage(sb, ws, m0, n0, (ks + 2) * BK, tid);
        else CP_COMMIT();
        rs = (rs == 2) ? 0 : rs + 1;
        ws = (ws == 2) ? 0 : ws + 1;
    }

    #pragma unroll
    for (int i = 0; i < 2; ++i)
        #pragma unroll
        for (int j = 0; j < 4; ++j)
            wmma::store_matrix_sync(out + (size_t)(m0 + wm * 32 + i * 16) * D + n0 + wn * 64 + j * 16,
                                    c[i][j], D, wmma::mem_row_major);
}

// ================= persistent HMMA recurrence: EXACT R11 (proven 2582us) =================
__global__ void __launch_bounds__(256, 1) rnn_mma(float* __restrict__ out,
                                                  const float* __restrict__ Ub,
                                                  const float* __restrict__ bias) {
    extern __shared__ char sm[];
    __nv_bfloat16* s_uhi = (__nv_bfloat16*)sm;             // [32][ULD] (init only)
    __nv_bfloat16* s_ulo = s_uhi + U_ELEMS;
    __nv_bfloat16* s_hhi = (__nv_bfloat16*)(sm + U_REGION); // [16][ULD], warp-private slabs
    __nv_bfloat16* s_hlo = s_hhi + H_ELEMS;
    float* s_red = (float*)sm;                             // ALIAS of U region: [2][8][512]
    float* s_wx  = s_red + 2 * 8 * 512;                    // [3][512]

    const int tid = threadIdx.x, warp = tid >> 5, lane = tid & 31;
    const int ni = blockIdx.x >> 2, bi = blockIdx.x & 3;
    const int n0 = ni * 32, b0 = bi * 16;

    // ---- stage U slice once ----
    {
        uint32_t duh = smem_u32(s_uhi), dul = smem_u32(s_ulo);
        for (int i = tid; i < 32 * 128; i += 256) {
            int r = i >> 7, c = i & 127;
            cp_async16(duh + (r * ULD + c * 8) * 2, g_uhi + (size_t)(n0 + r) * D + c * 8);
            cp_async16(dul + (r * ULD + c * 8) * 2, g_ulo + (size_t)(n0 + r) * D + c * 8);
        }
        CP_COMMIT();
        asm volatile("cp.async.wait_group 0;" ::: "memory");
        __syncthreads();
    }

    const int kc0 = warp * 128;

    // register-pinned U fragments (loaded before the alias region is written)
    wmma::fragment<wmma::matrix_b, 16, 16, 16, __nv_bfloat16, wmma::col_major> pbh[8][2], pbl[8][2];
    #pragma unroll
    for (int ks = 0; ks < 8; ++ks) {
        const int kg = kc0 + ks * 16;
        #pragma unroll
        for (int j = 0; j < 2; ++j) {
            wmma::load_matrix_sync(pbh[ks][j], s_uhi + (size_t)(j * 16) * ULD + kg, ULD);
            wmma::load_matrix_sync(pbl[ks][j], s_ulo + (size_t)(j * 16) * ULD + kg, ULD);
        }
    }
    __syncthreads();   // all frag loads done -> U smem region may be reused (s_red/s_wx)

    const uint32_t shh = smem_u32(s_hhi), shl = smem_u32(s_hlo);
    const uint32_t swx = smem_u32(s_wx);

    // this warp's 32 producer-warp flags: one per lane
    unsigned* myflag = &g_flags[bi][(warp << 2) + (lane >> 3)][lane & 7][0];
    unsigned* pubflag = &g_flags[bi][ni][warp][0];

    // ---- wx prefetch geometry: threads 0..127 move one 16B chunk each ----
    const int pr = tid >> 3, pc = tid & 7;
    const float* wx_src0 = out + (size_t)(b0 + pr) * (T * D) + n0 + pc * 4;
    const uint32_t wx_doff = (pr * 32 + pc * 4) * 4;

    // ---- epilogue constants ----
    const int eb  = tid >> 4;
    const int enl = (tid & 15) * 2;
    float2 cconst;
    cconst.x = Ub[n0 + enl]     + bias[n0 + enl];
    cconst.y = Ub[n0 + enl + 1] + bias[n0 + enl + 1];
    const size_t obase = (size_t)(b0 + eb) * (T * D) + n0 + enl;
    const int    hbase = (b0 + eb) * D + n0 + enl;
    const int    efr   = enl >> 4;
    const int    ec    = enl & 15;

    // ---- prologue: prefetch wx[0] into wx buffer 0 ----
    if (tid < 128) cp_async16(swx + wx_doff, wx_src0);
    CP_COMMIT();

    int wb = 0;                                   // t % 3
    for (int t = 0; t < T; ++t) {
        const __nv_bfloat16* Hhi = g_hhi[t & 1];
        const __nv_bfloat16* Hlo = g_hlo[t & 1];
        const int nwb = (wb == 2) ? 0 : wb + 1;   // (t+1) % 3

        // ---- acquire-poll this warp's 32 producer warps (no-op at t=0) ----
        {
            unsigned v;
            do {
                asm volatile("ld.acquire.gpu.global.u32 %0, [%1];" : "=r"(v) : "l"(myflag) : "memory");
            } while (v < (unsigned)t);
        }
        __syncwarp();

        // ---- self-stage this warp's h slab (warp-private smem region) ----
        #pragma unroll
        for (int j = 0; j < 8; ++j) {
            int i = lane + j * 32;
            int r = i >> 4, c = i & 15;
            uint32_t off = (r * ULD + kc0 + c * 8) * 2;
            const size_t goff = (size_t)(b0 + r) * D + kc0 + c * 8;
            cp_async16(shh + off, Hhi + goff);
            cp_async16(shl + off, Hlo + goff);
        }
        CP_COMMIT();

        // ---- prefetch wx[t+1] into buffer (t+1)%3 ----
        if (t + 1 < T && tid < 128)
            cp_async16(swx + nwb * 2048 + wx_doff, wx_src0 + (size_t)(t + 1) * D);
        CP_COMMIT();

        // completes h[t] and wx[t]; wx[t+1] may still fly
        asm volatile("cp.async.wait_group 1;" ::: "memory");
        __syncwarp();

        // ---- compute: M=16(b) x N=32 x K=128, 3 products, U from registers ----
        wmma::fragment<wmma::accumulator, 16, 16, 16, float> acc[2];
        wmma::fill_fragment(acc[0], 0.f);
        wmma::fill_fragment(acc[1], 0.f);
        #pragma unroll
        for (int ks = 0; ks < 8; ++ks) {
            const int kg = kc0 + ks * 16;
            wmma::fragment<wmma::matrix_a, 16, 16, 16, __nv_bfloat16, wmma::row_major> ah, al;
            wmma::load_matrix_sync(ah, s_hhi + kg, ULD);
            wmma::load_matrix_sync(al, s_hlo + kg, ULD);
            #pragma unroll
            for (int j = 0; j < 2; ++j) {
                wmma::mma_sync(acc[j], ah, pbh[ks][j], acc[j]);
                wmma::mma_sync(acc[j], al, pbh[ks][j], acc[j]);
                wmma::mma_sync(acc[j], ah, pbl[ks][j], acc[j]);
            }
        }
        float* red = s_red + (t & 1) * 4096;
        wmma::store_matrix_sync(red + warp * 512,       acc[0], 16, wmma::mem_row_major);
        wmma::store_matrix_sync(red + warp * 512 + 256, acc[1], 16, wmma::mem_row_major);
        __syncthreads();   // the ONE block sync per step

        // ---- 8-way K reduction + epilogue: h stores -> flag -> out store ----
        {
            const float* p = red + efr * 256 + eb * 16 + ec;
            float s0 = 0.f, s1 = 0.f;
            #pragma unroll
            for (int w = 0; w < 8; ++w) { s0 += p[w * 512]; s1 += p[w * 512 + 1]; }
            const float* wxp = s_wx + wb * 512 + eb * 32 + enl;
            float zx = tanhf(wxp[0] + s0 + cconst.x);
            float zy = tanhf(wxp[1] + s1 + cconst.y);

            // h stores FIRST (these are what consumers need)
            __nv_bfloat16 hx = __float2bfloat16(zx), hy = __float2bfloat16(zy);
            *(__nv_bfloat162*)(g_hhi[(t + 1) & 1] + hbase) = __nv_bfloat162(hx, hy);
            *(__nv_bfloat162*)(g_hlo[(t + 1) & 1] + hbase) =
                __nv_bfloat162(__float2bfloat16(zx - __bfloat162float(hx)),
                               __float2bfloat16(zy - __bfloat162float(hy)));
            __syncwarp();
            if (lane == 0)
                asm volatile("st.release.gpu.global.u32 [%0], %1;"
                             :: "l"(pubflag), "r"((unsigned)(t + 1)) : "memory");

            // out store off the critical path
            *(float2*)(out + obase + (size_t)t * D) = make_float2(zx, zy);
            if (t == T - 1)   // fused copy_hx
                *(float2*)(out + (size_t)B * T * D + hbase) = make_float2(zx, zy);
        }
        wb = nwb;
    }
}

extern "C" void kernel_launch(void* const* d_in, const int* in_sizes, int n_in,
                              void* d_out, int out_size) {
    const float* x    = (const float*)d_in[0];
    const float* Ww   = (const float*)d_in[1];
    const float* Wb   = (const float*)d_in[2];
    const float* Uw   = (const float*)d_in[3];
    const float* Ub   = (const float*)d_in[4];
    const float* bias = (const float*)d_in[5];
    float* out = (float*)d_out;

    cudaFuncSetAttribute(gemm_wx_mma, cudaFuncAttributeMaxDynamicSharedMemorySize, GEMM_SMEM);
    cudaFuncSetAttribute(rnn_mma,     cudaFuncAttributeMaxDynamicSharedMemorySize, RNN_SMEM);

    zero_h0<<<(B * D + 255) / 256, 256>>>();
    split_x<<<((size_t)B * T * D / 4) / 256, 256>>>(x);
    split_w<<<(D * D / 4) / 256, 256>>>(Ww);
    split_U<<<(D * D / 4) / 256, 256>>>(Uw);
    gemm_wx_mma<<<dim3(D / BN, (B * T) / BM), 256, GEMM_SMEM>>>(out, Wb);
    rnn_mma<<<RBLK, 256, RNN_SMEM>>>(out, Ub, bias);
}